// round 15
// baseline (speedup 1.0000x reference)
#include <cuda_runtime.h>

// SpectralConv2d (FNO spectral block), fused single kernel.
// out[b,l,o,h,w] = sum_c x[b,l,c,h,w] * w{1,2}[c,o,h',w] (complex), active only in
// two 16x16 mode corners (h 0..15 with w1, h 48..63 with w2); zero elsewhere.
// Output layout [B,L,O,H,W,2] f32 (re/im interleaved, = stack([re,im], -1)).
//
// R11 MEASURED (only datapoint): 39.7us, DRAM 21% / L2 24% / L1 52% / fma 21.6%
// / issue 29.8% / occ 40.3% -> latency-bound, nothing saturated. Root cause:
// unroll-1 inner loop exposed the ~250-cyc L2 weight-LDG latency every c-iter.
// FIX (this kernel, submitted unchanged since R12): register double-buffer
// prefetch — issue iteration c+1's weight loads (predicated @P LDG, running
// pointers so the loop-head LDG has no address-computation dependency) before
// iteration c's 32 fma2s. Cover = 4 warps x 32 fma2 x rt2 ≈ 256 SMSP-cyc >=
// ~250-cyc L2 latency -> weight latency hidden; loop becomes FMA-rate-bound.
// ~58 live regs < 64-reg launch_bounds(512,2) cap (2x512x64 = exact RF fill).
// Occupancy branch CLOSED: 40.3% measured ≈ 0.8x of the 50% cap (wave dilution,
// 4.4 waves) — RF is exactly full, more warps impossible; latency must be
// hidden per-warp, i.e. exactly this prefetch.
//
// Grid = 1312 blocks x 512 threads, roles INTERLEAVED in bid-space:
//   bid % 5 == 0 && bid < 1280 -> corner block, c_idx = bid/5   (256 total)
//   otherwise                  -> zero-fill block (1056 total, h=16..47)
// Corner block: blt(8) x mode-row i(16) x region r(2); 16 bl-samples x 32 o x
// 16 j at one h, plus zeroing the w=16..32 tail of its rows.
//
// LOAD-BEARING LAYOUT PROPERTY (do not change the thread map): j = tid&15 means
// lanes 0-15 and 16-31 read IDENTICAL smem addresses in the inner loop -> 16
// distinct 8B addresses per LDS.64 = 1 crossbar cycle (broadcast free). BPAD=18
// is the unique minimal even conflict-free pad ((18j)%32 pair-banks distinct).
// x staging stays scalar (odd W=33 -> wide LDG would trap err715).
// fma.rn.f32x2 is PTX-only FFMA2; per-lane rounding identical to scalar FFMA.
//
// NEXT-PROFILE DECISION TABLE: fma>=40% + dur 16-22us -> prefetch worked; check
// what binds next (watch l1tex: was 52.3%, ceiling ~20us if binding). dur>=25us
// with fma<30% -> latency model wrong: switch BLT 16->8 (512 finer corner
// blocks; L2 at 24% tolerates 2x weight traffic). Spills (LDL/STL) -> 384 thr.

#define BL 128
#define CIN 32
#define OCH 32
#define M1 16
#define M2 16
#define HH 64
#define WW 33
#define BLT 16
#define BPAD 18

#define NTHR 512
#define NCORNER 256              // 8 blt * 16 i * 2 regions
#define NZBLK 1056               // 4096 chunks * 528 f4 / (512 thr * 4 f4)
#define NGRID (NCORNER + NZBLK)  // 1312
#define XS_HALF (CIN * M2 * BPAD)            // 9216 floats per re/im array
#define SMEM_BYTES (2 * XS_HALF * 4)         // 73728
#define STRIDE_BLO (OCH * HH * WW)           // 67584 float2 between bl samples

typedef unsigned long long u64;

__device__ __forceinline__ u64 pack2(float v) {
    u64 r;
    asm("mov.b64 %0, {%1, %1};" : "=l"(r) : "f"(v));
    return r;
}
__device__ __forceinline__ float2 unpack2(u64 v) {
    float2 f;
    asm("mov.b64 {%0, %1}, %2;" : "=f"(f.x), "=f"(f.y) : "l"(v));
    return f;
}
__device__ __forceinline__ u64 fma2(u64 a, u64 b, u64 c) {
    u64 d;
    asm("fma.rn.f32x2 %0, %1, %2, %3;" : "=l"(d) : "l"(a), "l"(b), "l"(c));
    return d;
}

__global__ __launch_bounds__(NTHR, 2)
void spectral_fused_kernel(const float* __restrict__ x_re,
                           const float* __restrict__ x_im,
                           const float* __restrict__ w1_re,
                           const float* __restrict__ w1_im,
                           const float* __restrict__ w2_re,
                           const float* __restrict__ w2_im,
                           float2* __restrict__ out,
                           float4* __restrict__ out4) {
    extern __shared__ __align__(16) float xs[];   // [2][CIN][M2][BPAD]

    const int bid = blockIdx.x;
    const int tid = threadIdx.x;

    const bool is_corner = (bid % 5 == 0) && (bid < 5 * NCORNER);

    if (!is_corner) {
        // ---- Zero middle rows h=16..47. Per (bl,o) chunk of 1056 f4, the
        //      middle is f4 [264, 792): 528 contiguous f4. Coverage exact:
        //      1056 blocks * 2048 f4 = 4096 chunks * 528. ----
        int ncb = (bid + 4) / 5;                 // corner blocks strictly before bid
        if (ncb > NCORNER) ncb = NCORNER;
        const int z_idx = bid - ncb;             // 0..1055, continuous (audited)

        const int base = z_idx * 2048;
        #pragma unroll
        for (int k = 0; k < 4; k++) {
            const int idx   = base + k * NTHR + tid;   // < 2,162,688 exactly
            const int chunk = idx / 528;
            const int pos   = idx - chunk * 528;
            out4[chunk * 1056 + 264 + pos] = make_float4(0.f, 0.f, 0.f, 0.f);
        }
        return;
    }

    // ---- Corner compute block ----
    const int c_idx = bid / 5;
    const int blt = c_idx & 7;           // bl tile (0..7)
    const int i   = (c_idx >> 3) & 15;   // mode row
    const int r   = c_idx >> 7;          // 0: top (w1), 1: bottom (w2)

    const int h = (r == 0) ? i : (HH - M1 + i);
    const float* __restrict__ wr = (r == 0) ? w1_re : w2_re;
    const float* __restrict__ wi = (r == 0) ? w1_im : w2_im;

    // Stage x corner tile [b][c][j] -> smem [c][j][b]; scalar, coalesced.
    // Fully unrolled (16 iters) so ptxas can front-batch the LDGs (high MLP).
    #pragma unroll
    for (int idx = tid; idx < BLT * CIN * M2; idx += NTHR) {
        const int b = idx >> 9;                   // / (CIN*M2)
        const int c = (idx >> 4) & 31;
        const int j = idx & 15;
        const int g = (((blt * BLT + b) * CIN + c) * HH + h) * WW + j;
        const int s = (c * M2 + j) * BPAD + b;
        xs[s]           = x_re[g];
        xs[s + XS_HALF] = x_im[g];
    }

    // Zero the w=16..32 tail of this block's output rows (overlaps staging).
    #pragma unroll
    for (int idx = tid; idx < BLT * OCH * 17; idx += NTHR) {
        const int t = idx % 17;
        const int q = idx / 17;                   // q = b*32 + o
        const int b = q >> 5, o = q & 31;
        const int g = (((blt * BLT + b) * OCH + o) * HH + h) * WW + M2 + t;
        out[g] = make_float2(0.f, 0.f);
    }
    __syncthreads();

    // Each thread: one mode col j, one output channel o, all 16 bl samples as
    // 8 packed f32x2 pairs. Weights register-prefetched one c-iter ahead.
    const int j = tid & 15;
    const int o = tid >> 4;

    u64 ar[8], ai[8];
    #pragma unroll
    for (int p = 0; p < 8; p++) { ar[p] = ai[p] = 0ULL; }

    const int wbase = (o * M1 + i) * M2 + j;    // weight layout [C, O, M1, M2]
    const int WS_C  = OCH * M1 * M2;            // 8192

    const float* xr_row = xs + j * BPAD;
    const float* xi_row = xr_row + XS_HALF;

    // Running weight pointers: the prefetch LDG at loop-head has no address
    // computation in front of it (pure pointer bump at loop tail).
    const float* wrp = wr + wbase + WS_C;
    const float* wip = wi + wbase + WS_C;

    // Prologue: load c=0 weights.
    float w_r = wr[wbase];
    float w_i = wi[wbase];

    #pragma unroll 1
    for (int c = 0; c < CIN; c++) {
        // Prefetch next iteration's weights BEFORE this iteration's FMAs:
        // the 32 fma2 below (~256 SMSP-cyc at 4 warps) cover the L2 latency.
        float nw_r = 0.f, nw_i = 0.f;
        if (c + 1 < CIN) {
            nw_r = *wrp;
            nw_i = *wip;
        }

        const u64 wr2  = pack2(w_r);
        const u64 wi2  = pack2(w_i);
        const u64 nwi2 = pack2(-w_i);

        const float* xr_p = xr_row + c * (M2 * BPAD);
        const float* xi_p = xi_row + c * (M2 * BPAD);
        #pragma unroll
        for (int p = 0; p < 8; p++) {
            const u64 xr2 = *(const u64*)(xr_p + 2 * p);   // {b=2p, b=2p+1}
            const u64 xi2 = *(const u64*)(xi_p + 2 * p);
            ar[p] = fma2(xr2, wr2,  ar[p]);
            ar[p] = fma2(xi2, nwi2, ar[p]);
            ai[p] = fma2(xr2, wi2,  ai[p]);
            ai[p] = fma2(xi2, wr2,  ai[p]);
        }

        w_r = nw_r;
        w_i = nw_i;
        wrp += WS_C;
        wip += WS_C;
    }

    // Write computed corners: 16 consecutive j per (bl,o,h) row, coalesced.
    #pragma unroll
    for (int p = 0; p < 8; p++) {
        const int bl   = blt * BLT + 2 * p;
        const int base = ((bl * OCH + o) * HH + h) * WW + j;
        const float2 re = unpack2(ar[p]);
        const float2 im = unpack2(ai[p]);
        out[base]              = make_float2(re.x, im.x);
        out[base + STRIDE_BLO] = make_float2(re.y, im.y);   // bl+1
    }
}

extern "C" void kernel_launch(void* const* d_in, const int* in_sizes, int n_in,
                              void* d_out, int out_size) {
    const float* x_re  = (const float*)d_in[0];
    const float* x_im  = (const float*)d_in[1];
    const float* w1_re = (const float*)d_in[2];
    const float* w1_im = (const float*)d_in[3];
    const float* w2_re = (const float*)d_in[4];
    const float* w2_im = (const float*)d_in[5];

    // Non-stream API: capture-legal, not an allocation; needed for 72KB smem.
    cudaFuncSetAttribute(spectral_fused_kernel,
                         cudaFuncAttributeMaxDynamicSharedMemorySize, SMEM_BYTES);

    spectral_fused_kernel<<<NGRID, NTHR, SMEM_BYTES>>>(
        x_re, x_im, w1_re, w1_im, w2_re, w2_im,
        (float2*)d_out, (float4*)d_out);
}

// round 17
// speedup vs baseline: 1.1161x; 1.1161x over previous
#include <cuda_runtime.h>

// SpectralConv2d (FNO spectral block), fused single kernel.
// out[b,l,o,h,w] = sum_c x[b,l,c,h,w] * w{1,2}[c,o,h',w] (complex), active only in
// two 16x16 mode corners (h 0..15 w/ w1, h 48..63 w/ w2); zero elsewhere.
// Output layout [B,L,O,H,W,2] f32 (re/im interleaved, = stack([re,im], -1)).
//
// MEASURED HISTORY:
//  R11 (BLT=16, 512thr, occ2, unroll1):        39.7us, fma 21.6, issue 29.8
//  R15 (same + weight reg-prefetch):           39.7us, fma 22.0, issue 31.6
// Prefetch NEUTRAL -> weight-LDG latency was NOT the stall. fma=22% of the
// 64K-cyc runtime = only ~14K cyc of real FMA2 work; chip stalled ~70% of
// cycles. Surviving hypothesis: CORNER-WORK CONCENTRATION — only 256 corner
// blocks (1.73/SM), each a long serial 32-iter loop; zero blocks retire fast;
// SMs sit with 1-2 long corner CTAs that can't hide their own latency
// (T_total ≈ 2 x T_corner, insensitive to intra-loop fixes — exactly what the
// neutral prefetch showed).
//
// FIX UNDER TEST (unchanged since R16): spread the corner work.
//  - BLT 16->8: 512 corner blocks (3.5/SM), 40KB static smem, half the
//    per-CTA serial span.
//  - 256 threads, launch_bounds(256,4): 4 CTAs/SM (4x256x64 = exact RF fill;
//    4x40KB = 160KB < ~227KB smem). 4 independent CTAs per SM to interleave.
//  - Thread map (R5-audited): j = tid&15, o0 = (tid>>4)*2 — 2 output channels
//    x 8 bl per thread = 16 u64 accums. Reg audit (recounted R17): 32 acc +
//    12 weight-pack + 4 x-temps + ~12 addr ≈ 60 live < 64 cap, no spills.
//    Per iter: 8 LDS.64 + 32 fma2 (same FMA total, HALF the LDS of R15).
//  - Grid 1568, corner every 3rd bid (R4-audited mapping).
//  - Prefetch dropped (measured neutral).
//
// LOAD-BEARING PROPERTIES (audited): lanes l and l+16 read identical smem
// addresses (j=tid&15) -> 16 distinct 8B addrs per LDS.64 = 1 crossbar phase;
// BPAD=10 pair-banks (10j)%32 all distinct -> conflict-free; x staging scalar
// (odd W=33, wide LDG would trap err715); fma.rn.f32x2 = PTX-only FFMA2,
// per-lane rounding == scalar FFMA.
//
// NEXT-PROFILE DECISION: dur 20-26us + issue>=50% -> hypothesis confirmed,
// iterate on whatever binds next. dur ~39us unchanged -> limiter is OUTSIDE the
// corner loop (store path / L1tex, 52% both profiles): split zero-fill into a
// separate kernel to isolate, and pull per-instruction stall reasons.

#define BL 128
#define CIN 32
#define OCH 32
#define M1 16
#define M2 16
#define HH 64
#define WW 33
#define BLT 8
#define BPAD 10

#define NTHR 256
#define NCORNER 512              // 16 blt * 16 i * 2 regions
#define NZBLK 1056               // 4096 chunks * 528 f4 / (256 thr * 8 f4)
#define NGRID (NCORNER + NZBLK)  // 1568
#define XS_HALF (CIN * M2 * BPAD)            // 5120 floats per re/im array
#define STRIDE_O   (HH * WW)                 // 2112 float2 between output channels
#define STRIDE_BLO (OCH * HH * WW)           // 67584 float2 between bl samples

typedef unsigned long long u64;

__device__ __forceinline__ u64 pack2(float v) {
    u64 r;
    asm("mov.b64 %0, {%1, %1};" : "=l"(r) : "f"(v));
    return r;
}
__device__ __forceinline__ float2 unpack2(u64 v) {
    float2 f;
    asm("mov.b64 {%0, %1}, %2;" : "=f"(f.x), "=f"(f.y) : "l"(v));
    return f;
}
__device__ __forceinline__ u64 fma2(u64 a, u64 b, u64 c) {
    u64 d;
    asm("fma.rn.f32x2 %0, %1, %2, %3;" : "=l"(d) : "l"(a), "l"(b), "l"(c));
    return d;
}

__global__ __launch_bounds__(NTHR, 4)
void spectral_fused_kernel(const float* __restrict__ x_re,
                           const float* __restrict__ x_im,
                           const float* __restrict__ w1_re,
                           const float* __restrict__ w1_im,
                           const float* __restrict__ w2_re,
                           const float* __restrict__ w2_im,
                           float2* __restrict__ out,
                           float4* __restrict__ out4) {
    __shared__ __align__(16) float xs[2 * XS_HALF];   // 40KB: [2][CIN][M2][BPAD]

    const int bid = blockIdx.x;
    const int tid = threadIdx.x;

    const bool is_corner = (bid % 3 == 0) && (bid < 3 * NCORNER);

    if (!is_corner) {
        // ---- Zero middle rows h=16..47. Per (bl,o) chunk of 1056 f4, the
        //      middle is f4 [264, 792): 528 contiguous f4. Coverage exact:
        //      1056 blocks * 2048 f4 = 4096 chunks * 528 (R4-audited). ----
        int ncb = (bid + 2) / 3;                 // corner blocks strictly before bid
        if (ncb > NCORNER) ncb = NCORNER;
        const int z_idx = bid - ncb;             // 0..1055, continuous

        const int base = z_idx * 2048;
        #pragma unroll
        for (int k = 0; k < 8; k++) {
            const int idx   = base + k * NTHR + tid;   // < 2,162,688 exactly
            const int chunk = idx / 528;
            const int pos   = idx - chunk * 528;
            out4[chunk * 1056 + 264 + pos] = make_float4(0.f, 0.f, 0.f, 0.f);
        }
        return;
    }

    // ---- Corner compute block ----
    const int c_idx = bid / 3;
    const int blt = c_idx & 15;          // bl tile (0..15)
    const int i   = (c_idx >> 4) & 15;   // mode row
    const int r   = c_idx >> 8;          // 0: top (w1), 1: bottom (w2)

    const int h = (r == 0) ? i : (HH - M1 + i);
    const float* __restrict__ wr = (r == 0) ? w1_re : w2_re;
    const float* __restrict__ wi = (r == 0) ? w1_im : w2_im;

    // Stage x corner tile [b][c][j] -> smem [c][j][b]; scalar, coalesced.
    // 8 bl * 32 c * 16 j = 4096 elems per array, 16 iters of 256 threads.
    #pragma unroll
    for (int idx = tid; idx < BLT * CIN * M2; idx += NTHR) {
        const int b = idx >> 9;                   // / (CIN*M2)
        const int c = (idx >> 4) & 31;
        const int j = idx & 15;
        const int g = (((blt * BLT + b) * CIN + c) * HH + h) * WW + j;
        const int s = (c * M2 + j) * BPAD + b;
        xs[s]           = x_re[g];
        xs[s + XS_HALF] = x_im[g];
    }

    // Zero the w=16..32 tail of this block's output rows (overlaps staging).
    // 8 bl * 32 o * 17 cols = 4352 float2 stores, 17 iters of 256.
    #pragma unroll
    for (int idx = tid; idx < BLT * OCH * 17; idx += NTHR) {
        const int t = idx % 17;
        const int q = idx / 17;                   // q = b*32 + o
        const int b = q >> 5, o = q & 31;
        const int g = (((blt * BLT + b) * OCH + o) * HH + h) * WW + M2 + t;
        out[g] = make_float2(0.f, 0.f);
    }
    __syncthreads();

    // Each thread: one mode col j, TWO output channels (o0, o0+1), all 8 bl
    // samples as 4 packed f32x2 pairs per quantity (16 u64 accums).
    const int j  = tid & 15;
    const int o0 = (tid >> 4) << 1;   // 0,2,...,30

    u64 ar0[4], ai0[4], ar1[4], ai1[4];
    #pragma unroll
    for (int p = 0; p < 4; p++) { ar0[p] = ai0[p] = ar1[p] = ai1[p] = 0ULL; }

    const int wbase = (o0 * M1 + i) * M2 + j;   // weight layout [C, O, M1, M2]
    const int WS_C  = OCH * M1 * M2;            // 8192
    const int WS_O  = M1 * M2;                  // 256

    const float* xr_row = xs + j * BPAD;
    const float* xi_row = xr_row + XS_HALF;

    #pragma unroll 1
    for (int c = 0; c < CIN; c++) {
        const int wc = wbase + c * WS_C;
        const float w0r = wr[wc];
        const float w0i = wi[wc];
        const float w1r = wr[wc + WS_O];
        const float w1i = wi[wc + WS_O];
        const u64 w0r2  = pack2(w0r);
        const u64 w0i2  = pack2(w0i);
        const u64 nw0i2 = pack2(-w0i);
        const u64 w1r2  = pack2(w1r);
        const u64 w1i2  = pack2(w1i);
        const u64 nw1i2 = pack2(-w1i);

        const float* xr_p = xr_row + c * (M2 * BPAD);
        const float* xi_p = xi_row + c * (M2 * BPAD);
        #pragma unroll
        for (int p = 0; p < 4; p++) {
            const u64 xr2 = *(const u64*)(xr_p + 2 * p);   // {b=2p, b=2p+1}
            const u64 xi2 = *(const u64*)(xi_p + 2 * p);
            ar0[p] = fma2(xr2, w0r2,  ar0[p]);
            ar0[p] = fma2(xi2, nw0i2, ar0[p]);
            ai0[p] = fma2(xr2, w0i2,  ai0[p]);
            ai0[p] = fma2(xi2, w0r2,  ai0[p]);
            ar1[p] = fma2(xr2, w1r2,  ar1[p]);
            ar1[p] = fma2(xi2, nw1i2, ar1[p]);
            ai1[p] = fma2(xr2, w1i2,  ai1[p]);
            ai1[p] = fma2(xi2, w1r2,  ai1[p]);
        }
    }

    // Write computed corners: 16 consecutive j per (bl,o,h) row, coalesced.
    #pragma unroll
    for (int p = 0; p < 4; p++) {
        const int bl   = blt * BLT + 2 * p;
        const int base = ((bl * OCH + o0) * HH + h) * WW + j;
        const float2 re0 = unpack2(ar0[p]);
        const float2 im0 = unpack2(ai0[p]);
        const float2 re1 = unpack2(ar1[p]);
        const float2 im1 = unpack2(ai1[p]);
        out[base]                         = make_float2(re0.x, im0.x);
        out[base + STRIDE_O]              = make_float2(re1.x, im1.x);   // o0+1
        out[base + STRIDE_BLO]            = make_float2(re0.y, im0.y);   // bl+1
        out[base + STRIDE_BLO + STRIDE_O] = make_float2(re1.y, im1.y);
    }
}

extern "C" void kernel_launch(void* const* d_in, const int* in_sizes, int n_in,
                              void* d_out, int out_size) {
    const float* x_re  = (const float*)d_in[0];
    const float* x_im  = (const float*)d_in[1];
    const float* w1_re = (const float*)d_in[2];
    const float* w1_im = (const float*)d_in[3];
    const float* w2_re = (const float*)d_in[4];
    const float* w2_im = (const float*)d_in[5];

    spectral_fused_kernel<<<NGRID, NTHR>>>(
        x_re, x_im, w1_re, w1_im, w2_re, w2_im,
        (float2*)d_out, (float4*)d_out);
}